// round 9
// baseline (speedup 1.0000x reference)
#include <cuda_runtime.h>

#define T_STEPS 2048
#define N_RES   2048
#define D_IN    128
#define NCTA    128
#define NTHR    512
#define ROWS_PER_CTA 16
#define INV_SQRT_N 0.022097086912079608f  // 1/sqrt(2048)
#define SENT32 0x7FC00000u                // qNaN sentinel bit pattern

// Scratch: precomputed input projections U[t][n] (16 MB).
__device__ float g_U[(size_t)T_STEPS * N_RES];

// Prefill out with qNaN sentinel: real x values are erf(..)/sqrt(N), never NaN.
__global__ void esn_prefill(float4* __restrict__ out4) {
    const float qn = __uint_as_float(SENT32);
    const float4 nv = make_float4(qn, qn, qn, qn);
    const size_t total = (size_t)T_STEPS * N_RES / 4;
    const size_t stride = (size_t)gridDim.x * blockDim.x;
    for (size_t i = (size_t)blockIdx.x * blockDim.x + threadIdx.x; i < total; i += stride)
        out4[i] = nv;
}

__global__ void __launch_bounds__(NTHR, 1) esn_main(
    const float* __restrict__ input,   // [T, D]
    const float* __restrict__ W_in,    // [N, D]
    const float* __restrict__ W_res,   // [N, N]
    float* __restrict__ out)           // [T, N]  (row t == x_t)
{
    const int tid   = threadIdx.x;
    const int b     = blockIdx.x;
    const int rbase = b * ROWS_PER_CTA;
    const int l     = tid & 31;
    const int w     = tid >> 5;          // warp 0..15
    const int rowg  = w & 3;             // 4 row-groups of 4 rows
    const int colg  = w >> 2;            // 4 col-groups of 512 cols
    const int cbase = colg * 512;

    __shared__ float sh[2048];                 // W_in slice (phase U only)
    __shared__ float part_s[4][16][4];         // [t&3][row][colg], sentinel-flagged
    volatile float* part = &part_s[0][0][0];
    const float SENTF = __uint_as_float(SENT32);

    // ================= Phase U: U = input @ W_in^T (own 16 columns) ============
    ((float4*)sh)[tid] = ((const float4*)(W_in + (size_t)rbase * D_IN))[tid];
    if (tid < 256) part[tid] = SENTF;          // init all 4 depths to sentinel
    __syncthreads();

    for (int k = 0; k < 4; ++k) {
        const int t = tid + NTHR * k;
        float acc[16];
        #pragma unroll
        for (int n = 0; n < 16; ++n) acc[n] = 0.f;
        const float4* inrow = (const float4*)(input + (size_t)t * D_IN);
        for (int jd = 0; jd < 32; ++jd) {
            float4 iv = __ldg(inrow + jd);
            #pragma unroll
            for (int n = 0; n < 16; ++n) {
                float4 wv = ((const float4*)sh)[n * 32 + jd];
                acc[n] = fmaf(iv.x, wv.x, acc[n]);
                acc[n] = fmaf(iv.y, wv.y, acc[n]);
                acc[n] = fmaf(iv.z, wv.z, acc[n]);
                acc[n] = fmaf(iv.w, wv.w, acc[n]);
            }
        }
        float4* urow = (float4*)(g_U + (size_t)t * N_RES + rbase);
        #pragma unroll
        for (int q = 0; q < 4; ++q)
            urow[q] = make_float4(acc[4*q], acc[4*q+1], acc[4*q+2], acc[4*q+3]);
    }
    __syncthreads();

    // ============ Load recurrence weights into registers (64 floats/thread) ====
    unsigned long long wreg[4][8];
    #pragma unroll
    for (int i = 0; i < 4; ++i) {
        const float* wrow = W_res + (size_t)(rbase + rowg * 4 + i) * N_RES + cbase + 2 * l;
        #pragma unroll
        for (int j = 0; j < 8; ++j)
            wreg[i][j] = *(const unsigned long long*)(wrow + 64 * j);
    }

    // ================= t = 0: x0 = erf(U[0]) / sqrt(N)  (warp w owns row w) ====
    if (l == 0) {
        float u0 = g_U[rbase + w];
        __stcg(&out[rbase + w], erff(u0) * INV_SQRT_N);
    }

    // ================= Recurrence (barrier-free, distributed combine) ==========
    for (int t = 1; t < T_STEPS; ++t) {
        const int d = t & 3;
        float u = 0.f;
        if (l == 0) u = g_U[(size_t)t * N_RES + rbase + w];   // own-row U prefetch

        const float* xp = out + (size_t)(t - 1) * N_RES + cbase + 2 * l;

        // Speculative load (plain LDG: fresh lines; 4 warps/colgroup share L1).
        unsigned long long xr[8];
        #pragma unroll
        for (int j = 0; j < 8; ++j)
            xr[j] = *(const unsigned long long*)(xp + 64 * j);

        // Readiness = raw-bit compare of each 32-bit half vs sentinel;
        // retry reloads ONLY stale words, bypassing L1. Backoff after 2 rounds.
        unsigned bad = 0u;
        #pragma unroll
        for (int j = 0; j < 8; ++j) {
            unsigned lo = (unsigned)xr[j], hi = (unsigned)(xr[j] >> 32);
            bad |= (unsigned)((lo == SENT32) | (hi == SENT32)) << j;
        }
        int rounds = 0;
        while (__any_sync(0xFFFFFFFFu, bad != 0u)) {
            if (++rounds > 2) __nanosleep(50);
            #pragma unroll
            for (int j = 0; j < 8; ++j) {
                if (bad & (1u << j))
                    asm volatile("ld.global.cg.b64 %0, [%1];"
                                 : "=l"(xr[j]) : "l"(xp + 64 * j) : "memory");
            }
            bad = 0u;
            #pragma unroll
            for (int j = 0; j < 8; ++j) {
                unsigned lo = (unsigned)xr[j], hi = (unsigned)(xr[j] >> 32);
                bad |= (unsigned)((lo == SENT32) | (hi == SENT32)) << j;
            }
        }

        // Dot products: 4 rows x 16 cols per thread via packed f32x2 FMA.
        unsigned long long acc[4] = {0ull, 0ull, 0ull, 0ull};
        #pragma unroll
        for (int j = 0; j < 8; ++j) {
            #pragma unroll
            for (int i = 0; i < 4; ++i)
                asm volatile("fma.rn.f32x2 %0, %1, %2, %0;"
                             : "+l"(acc[i]) : "l"(wreg[i][j]), "l"(xr[j]));
        }
        float s[4];
        #pragma unroll
        for (int i = 0; i < 4; ++i) {
            float2 f = *reinterpret_cast<float2*>(&acc[i]);
            s[i] = f.x + f.y;
        }
        #pragma unroll
        for (int off = 16; off > 0; off >>= 1) {
            #pragma unroll
            for (int i = 0; i < 4; ++i)
                s[i] += __shfl_xor_sync(0xFFFFFFFFu, s[i], off);
        }

        if (l == 0) {
            // Publish 4 partials (value IS the flag; slots pre-reset to sentinel).
            #pragma unroll
            for (int i = 0; i < 4; ++i)
                part[(d * 16 + rowg * 4 + i) * 4 + colg] = s[i];

            // Combine own row (rbase + w): spin on its 4 colgroup slots.
            volatile float* myrow = part + (d * 16 + w) * 4;
            float v0, v1, v2, v3;
            do {
                v0 = myrow[0]; v1 = myrow[1]; v2 = myrow[2]; v3 = myrow[3];
            } while ((v0 != v0) | (v1 != v1) | (v2 != v2) | (v3 != v3));
            // Reset for reuse at t+4 (>= 3 global round-trips away).
            myrow[0] = SENTF; myrow[1] = SENTF; myrow[2] = SENTF; myrow[3] = SENTF;

            float pre = v0 + v1 + v2 + v3 + u;
            __stcg(&out[(size_t)t * N_RES + rbase + w], erff(pre) * INV_SQRT_N);
        }
        // Lanes 1..31 fall through and prefetch step t+1 while lane 0 combines;
        // they re-converge at the next __any_sync.
    }
}

extern "C" void kernel_launch(void* const* d_in, const int* in_sizes, int n_in,
                              void* d_out, int out_size)
{
    const float* input = (const float*)d_in[0];   // (2048, 128)
    const float* W_in  = (const float*)d_in[1];   // (2048, 128)
    const float* W_res = (const float*)d_in[2];   // (2048, 2048)
    float* out = (float*)d_out;                   // (2048, 2048)

    esn_prefill<<<NCTA, NTHR>>>((float4*)out);
    esn_main<<<NCTA, NTHR>>>(input, W_in, W_res, out);
}

// round 14
// speedup vs baseline: 4.4805x; 4.4805x over previous
#include <cuda_runtime.h>

#define T_STEPS 2048
#define N_RES   2048
#define D_IN    128
#define NCTA    128
#define NTHR    512
#define ROWS_PER_CTA 16
#define INV_SQRT_N 0.022097086912079608f  // 1/sqrt(2048)
#define SENT32 0x7FC00000u                // qNaN sentinel bit pattern

// Scratch: precomputed input projections U[t][n] (16 MB).
__device__ float g_U[(size_t)T_STEPS * N_RES];

// Prefill out with qNaN sentinel: real x values are erf(..)/sqrt(N), never NaN.
__global__ void esn_prefill(float4* __restrict__ out4) {
    const float qn = __uint_as_float(SENT32);
    const float4 nv = make_float4(qn, qn, qn, qn);
    const size_t total = (size_t)T_STEPS * N_RES / 4;
    const size_t stride = (size_t)gridDim.x * blockDim.x;
    for (size_t i = (size_t)blockIdx.x * blockDim.x + threadIdx.x; i < total; i += stride)
        out4[i] = nv;
}

__global__ void __launch_bounds__(NTHR, 1) esn_main(
    const float* __restrict__ input,   // [T, D]
    const float* __restrict__ W_in,    // [N, D]
    const float* __restrict__ W_res,   // [N, N]
    float* __restrict__ out)           // [T, N]  (row t == x_t)
{
    const int tid   = threadIdx.x;
    const int b     = blockIdx.x;
    const int rbase = b * ROWS_PER_CTA;
    const int l     = tid & 31;
    const int w     = tid >> 5;          // warp 0..15
    const int rowg  = w & 3;             // 4 row-groups of 4 rows
    const int colg  = w >> 2;            // 4 col-groups of 512 cols
    const int cbase = colg * 512;

    __shared__ float sh[2048];           // W_in slice (phase U only)
    __shared__ float part[2][4][16];     // ping-pong: [t&1][colg][row]

    // ================= Phase U: U = input @ W_in^T (own 16 columns) ============
    ((float4*)sh)[tid] = ((const float4*)(W_in + (size_t)rbase * D_IN))[tid];
    __syncthreads();

    for (int k = 0; k < 4; ++k) {
        const int t = tid + NTHR * k;
        float acc[16];
        #pragma unroll
        for (int n = 0; n < 16; ++n) acc[n] = 0.f;
        const float4* inrow = (const float4*)(input + (size_t)t * D_IN);
        for (int jd = 0; jd < 32; ++jd) {
            float4 iv = __ldg(inrow + jd);
            #pragma unroll
            for (int n = 0; n < 16; ++n) {
                float4 wv = ((const float4*)sh)[n * 32 + jd];
                acc[n] = fmaf(iv.x, wv.x, acc[n]);
                acc[n] = fmaf(iv.y, wv.y, acc[n]);
                acc[n] = fmaf(iv.z, wv.z, acc[n]);
                acc[n] = fmaf(iv.w, wv.w, acc[n]);
            }
        }
        float4* urow = (float4*)(g_U + (size_t)t * N_RES + rbase);
        #pragma unroll
        for (int q = 0; q < 4; ++q)
            urow[q] = make_float4(acc[4*q], acc[4*q+1], acc[4*q+2], acc[4*q+3]);
    }
    __syncthreads();

    // ============ Load recurrence weights into registers (64 floats/thread) ====
    unsigned long long wreg[4][8];
    #pragma unroll
    for (int i = 0; i < 4; ++i) {
        const float* wrow = W_res + (size_t)(rbase + rowg * 4 + i) * N_RES + cbase + 2 * l;
        #pragma unroll
        for (int j = 0; j < 8; ++j)
            wreg[i][j] = *(const unsigned long long*)(wrow + 64 * j);
    }

    // ================= t = 0: x0 = erf(U[0]) / sqrt(N) =========================
    if (w == 0 && l < 16) {
        float u0 = g_U[rbase + l];
        __stcg(&out[rbase + l], erff(u0) * INV_SQRT_N);
    }

    // ================= Recurrence (incremental-consume data-as-flag) ===========
    for (int t = 1; t < T_STEPS; ++t) {
        const int p = t & 1;
        float u = 0.f;
        if (w == 0 && l < 16) u = g_U[(size_t)t * N_RES + rbase + l];

        const float* xp = out + (size_t)(t - 1) * N_RES + cbase + 2 * l;

        // Speculative load (plain LDG: fresh lines; 4 warps/colgroup share L1).
        unsigned long long xr[8];
        #pragma unroll
        for (int j = 0; j < 8; ++j)
            xr[j] = *(const unsigned long long*)(xp + 64 * j);

        unsigned long long acc[4] = {0ull, 0ull, 0ull, 0ull};
        unsigned done = 0u;     // words already FMA'd into acc

        // Classify each 8B word by raw-bit sentinel compare (per 32-bit half,
        // handles tearing); FMA ready words immediately; retry ONLY stale words
        // with L1-bypassing loads. While retries are in flight, the scoreboard
        // lets the FMAs of already-arrived words execute under them.
        unsigned bad = 0u;
        #pragma unroll
        for (int j = 0; j < 8; ++j) {
            unsigned lo = (unsigned)xr[j], hi = (unsigned)(xr[j] >> 32);
            bad |= (unsigned)((lo == SENT32) | (hi == SENT32)) << j;
        }

        for (;;) {
            // Consume newly-ready words.
            const unsigned newly = ~bad & ~done & 0xFFu;
            #pragma unroll
            for (int j = 0; j < 8; ++j) {
                if ((newly >> j) & 1u) {
                    #pragma unroll
                    for (int i = 0; i < 4; ++i)
                        asm volatile("fma.rn.f32x2 %0, %1, %2, %0;"
                                     : "+l"(acc[i]) : "l"(wreg[i][j]), "l"(xr[j]));
                }
            }
            done |= newly;
            if (!__any_sync(0xFFFFFFFFu, done != 0xFFu)) break;

            // Re-poll stale words (fetch IS the poll).
            #pragma unroll
            for (int j = 0; j < 8; ++j) {
                if (bad & (1u << j))
                    asm volatile("ld.global.cg.b64 %0, [%1];"
                                 : "=l"(xr[j]) : "l"(xp + 64 * j) : "memory");
            }
            bad = 0u;
            #pragma unroll
            for (int j = 0; j < 8; ++j) {
                unsigned lo = (unsigned)xr[j], hi = (unsigned)(xr[j] >> 32);
                bad |= (unsigned)((lo == SENT32) | (hi == SENT32)) << j;
            }
        }

        float s[4];
        #pragma unroll
        for (int i = 0; i < 4; ++i) {
            float2 f = *reinterpret_cast<float2*>(&acc[i]);
            s[i] = f.x + f.y;
        }
        #pragma unroll
        for (int off = 16; off > 0; off >>= 1) {
            #pragma unroll
            for (int i = 0; i < 4; ++i)
                s[i] += __shfl_xor_sync(0xFFFFFFFFu, s[i], off);
        }
        if (l == 0) {
            #pragma unroll
            for (int i = 0; i < 4; ++i)
                part[p][colg][rowg * 4 + i] = s[i];
        }
        __syncthreads();   // single barrier/step: handoff + pacing

        if (w == 0 && l < 16) {
            float pre = part[p][0][l] + part[p][1][l] + part[p][2][l]
                      + part[p][3][l] + u;
            __stcg(&out[(size_t)t * N_RES + rbase + l], erff(pre) * INV_SQRT_N);
        }
    }
}

extern "C" void kernel_launch(void* const* d_in, const int* in_sizes, int n_in,
                              void* d_out, int out_size)
{
    const float* input = (const float*)d_in[0];   // (2048, 128)
    const float* W_in  = (const float*)d_in[1];   // (2048, 128)
    const float* W_res = (const float*)d_in[2];   // (2048, 2048)
    float* out = (float*)d_out;                   // (2048, 2048)

    esn_prefill<<<NCTA, NTHR>>>((float4*)out);
    esn_main<<<NCTA, NTHR>>>(input, W_in, W_res, out);
}